// round 9
// baseline (speedup 1.0000x reference)
#include <cuda_runtime.h>
#include <math.h>

#define NBINS    16384
#define DIM      1024
#define MULT     128
#define ROWLEN   (DIM * MULT)   // 131072 elements per batch row
#define NTHREADS 1024

// ---------------------------------------------------------------------------
// XLA:CPU vectorized expf (GenerateVF32Exp, Cephes) as contracted on aarch64.
// R5 vs R8 proved fused/unfused reduction identical on these inputs.
// ---------------------------------------------------------------------------
__device__ __forceinline__ float exp_ref(float xin) {
    float x = fminf(xin, 88.3762626647950f);
    x = fmaxf(x, -88.3762626647949f);
    float fx = floorf(__fmaf_rn(x, 1.44269504088896341f, 0.5f));
    x = __fmaf_rn(fx, -0.693359375f, x);
    x = __fmaf_rn(fx,  2.12194440e-4f, x);
    float z2 = __fmul_rn(x, x);
    float y = __fmaf_rn(1.9875691500E-4f, x, 1.3981999507E-3f);
    y = __fmaf_rn(y, x, 8.3334519073E-3f);
    y = __fmaf_rn(y, x, 4.1665795894E-2f);
    y = __fmaf_rn(y, x, 1.6666665459E-1f);
    y = __fmaf_rn(y, x, 5.0000001201E-1f);
    y = __fmaf_rn(y, z2, x);
    y = __fadd_rn(y, 1.0f);
    int n = (int)fx;
    float scale = __int_as_float((n + 127) << 23);
    float r = __fmul_rn(y, scale);
    return fmaxf(r, xin);
}

// Dynamic shared: the 16384-bin histogram (64 KB)
extern __shared__ int sh_hist[];

__global__ void __launch_bounds__(NTHREADS, 1)
pd_kernel(const float* __restrict__ z_mean, const float* __restrict__ z_var,
          const float* __restrict__ x, const float* __restrict__ eps,
          float* __restrict__ out)
{
    __shared__ float s_redA[32];
    __shared__ float s_redB[32];
    __shared__ float s_mn, s_recip, s_sum;
    __shared__ int   s_redI[32];
    __shared__ int   s_cmax;

    const int b    = blockIdx.x;
    const int t    = threadIdx.x;
    const int lane = t & 31;
    const int warp = t >> 5;

    // Each thread owns a fixed float4 column of the dim axis: d4 = t % 256.
    const int d4 = t & 255;
    const float4 m4 = reinterpret_cast<const float4*>(z_mean + (size_t)b * DIM)[d4];
    const float4 v4 = reinterpret_cast<const float4*>(z_var  + (size_t)b * DIM)[d4];
    float4 sg;
    sg.x = exp_ref(__fmul_rn(0.5f, v4.x));
    sg.y = exp_ref(__fmul_rn(0.5f, v4.y));
    sg.z = exp_ref(__fmul_rn(0.5f, v4.z));
    sg.w = exp_ref(__fmul_rn(0.5f, v4.w));

    const float4* e4 = reinterpret_cast<const float4*>(eps + (size_t)b * ROWLEN);
    const int r0 = t >> 8;  // 0..3 : which group of repeat-rows this thread covers

    // ---------------- Pass A: row min / max ----------------
    // Un-jitted jax: mul and add are SEPARATE XLA ops -> two roundings.
    float vmin = INFINITY, vmax = -INFINITY;
    #pragma unroll 4
    for (int r = r0; r < MULT; r += 4) {
        float4 e = e4[r * 256 + d4];
        float z0 = __fadd_rn(m4.x, __fmul_rn(sg.x, e.x));
        float z1 = __fadd_rn(m4.y, __fmul_rn(sg.y, e.y));
        float z2 = __fadd_rn(m4.z, __fmul_rn(sg.z, e.z));
        float z3 = __fadd_rn(m4.w, __fmul_rn(sg.w, e.w));
        vmin = fminf(vmin, fminf(fminf(z0, z1), fminf(z2, z3)));
        vmax = fmaxf(vmax, fmaxf(fmaxf(z0, z1), fmaxf(z2, z3)));
    }
    #pragma unroll
    for (int o = 16; o; o >>= 1) {
        vmin = fminf(vmin, __shfl_xor_sync(0xffffffffu, vmin, o));
        vmax = fmaxf(vmax, __shfl_xor_sync(0xffffffffu, vmax, o));
    }
    if (lane == 0) { s_redA[warp] = vmin; s_redB[warp] = vmax; }
    __syncthreads();
    if (warp == 0) {
        float a = s_redA[lane], m = s_redB[lane];
        #pragma unroll
        for (int o = 16; o; o >>= 1) {
            a = fminf(a, __shfl_xor_sync(0xffffffffu, a, o));
            m = fmaxf(m, __shfl_xor_sync(0xffffffffu, m, o));
        }
        if (lane == 0) {
            s_mn = a;
            // Reference (XLA:CPU fast-math, arcp + LICM): the per-row division
            // becomes ONE correctly-rounded reciprocal, then per-element mul.
            s_recip = __fdiv_rn(1.0f, __fsub_rn(m, a));
        }
    }
    // zero the histogram while the reduce settles
    #pragma unroll
    for (int i = t; i < NBINS; i += NTHREADS) sh_hist[i] = 0;
    __syncthreads();

    const float mn    = s_mn;
    const float recip = s_recip;

    // ---------------- Pass B: histogram ----------------
    // scaled = ((z - mn) * recip) * 16384, exactly three roundings
    // (the *16384 is an exact pow-2 scale), then trunc + clamp.
    #pragma unroll 4
    for (int r = r0; r < MULT; r += 4) {
        float4 e = e4[r * 256 + d4];
        float zz[4];
        zz[0] = __fadd_rn(m4.x, __fmul_rn(sg.x, e.x));
        zz[1] = __fadd_rn(m4.y, __fmul_rn(sg.y, e.y));
        zz[2] = __fadd_rn(m4.z, __fmul_rn(sg.z, e.z));
        zz[3] = __fadd_rn(m4.w, __fmul_rn(sg.w, e.w));
        #pragma unroll
        for (int j = 0; j < 4; j++) {
            float s  = __fmul_rn(__fsub_rn(zz[j], mn), recip);
            float a  = __fmul_rn(s, 16384.0f);
            int   ia = (int)a;
            ia = ia < 0 ? 0 : (ia > NBINS - 1 ? NBINS - 1 : ia);
            atomicAdd(&sh_hist[ia], 1);
        }
    }
    __syncthreads();

    // ---------------- Softmax over counts ----------------
    int cmax = 0;
    #pragma unroll
    for (int i = t; i < NBINS; i += NTHREADS) cmax = max(cmax, sh_hist[i]);
    #pragma unroll
    for (int o = 16; o; o >>= 1) cmax = max(cmax, __shfl_xor_sync(0xffffffffu, cmax, o));
    if (lane == 0) s_redI[warp] = cmax;
    __syncthreads();
    if (warp == 0) {
        int c = s_redI[lane];
        #pragma unroll
        for (int o = 16; o; o >>= 1) c = max(c, __shfl_xor_sync(0xffffffffu, c, o));
        if (lane == 0) s_cmax = c;
    }
    __syncthreads();
    const float fcmax = (float)s_cmax;

    // exp(count - max); overwrite histogram slots (each slot owned by one thread)
    float sum = 0.f;
    float* sh_f = reinterpret_cast<float*>(sh_hist);
    #pragma unroll
    for (int k = 0; k < NBINS / NTHREADS; k++) {
        int i = t + k * NTHREADS;
        float ev = exp_ref(__fsub_rn((float)sh_hist[i], fcmax));
        sh_f[i] = ev;
        sum += ev;
    }
    #pragma unroll
    for (int o = 16; o; o >>= 1) sum += __shfl_xor_sync(0xffffffffu, sum, o);
    if (lane == 0) s_redA[warp] = sum;
    __syncthreads();
    if (warp == 0) {
        float s2 = s_redA[lane];
        #pragma unroll
        for (int o = 16; o; o >>= 1) s2 += __shfl_xor_sync(0xffffffffu, s2, o);
        if (lane == 0) s_sum = s2;
    }
    __syncthreads();
    const float Z = s_sum;

    // ---------------- Gate x and write out ----------------
    const float* xb = x   + (size_t)b * NBINS;
    float*       ob = out + (size_t)b * NBINS;
    #pragma unroll
    for (int k = 0; k < NBINS / NTHREADS; k++) {
        int i = t + k * NTHREADS;
        float p = __fdiv_rn(sh_f[i], Z);
        if (p < 1e-10f) p = 0.f;
        ob[i] = __fmul_rn(__fmul_rn(xb[i], p), 128.0f);
    }
}

extern "C" void kernel_launch(void* const* d_in, const int* in_sizes, int n_in,
                              void* d_out, int out_size)
{
    const float* z_mean = (const float*)d_in[0];
    const float* z_var  = (const float*)d_in[1];
    const float* x      = (const float*)d_in[2];
    const float* eps    = (const float*)d_in[3];
    float*       out    = (float*)d_out;

    cudaFuncSetAttribute(pd_kernel, cudaFuncAttributeMaxDynamicSharedMemorySize,
                         NBINS * (int)sizeof(int));
    pd_kernel<<<128, NTHREADS, NBINS * sizeof(int)>>>(z_mean, z_var, x, eps, out);
}